// round 2
// baseline (speedup 1.0000x reference)
#include <cuda_runtime.h>
#include <cstdint>

#define NROWS 8192
#define DIM   128
#define BM    128
#define BN    128
#define NTILES (NROWS / BN)          // 64
#define JSPLIT 2
#define TILES_PER (NTILES / JSPLIT)  // 32
#define MARGIN_F 0.3f

// Scratch (device globals; no allocations allowed)
__device__ unsigned int g_ap2[NROWS];   // max same-label d^2 (float bits)
__device__ unsigned int g_an2[NROWS];   // min diff-label d^2 (float bits)
__device__ float        g_sq[NROWS];    // ||x_i||^2
__device__ int          g_lab[NROWS];   // normalized labels (int32)

// ---------------------------------------------------------------------------
// Label prep: targets may be int64 (reference declares int64) or int32 (JAX
// x64-disabled demotion). Values are in [0, 512). If int64 little-endian, the
// int32 view is [v0,0,v1,0,...]; detect "all odd words zero" over the first
// 4096 rows (in-bounds for both interpretations) and normalize.
// ---------------------------------------------------------------------------
__global__ void prep_labels_kernel(const int* __restrict__ t32) {
    __shared__ int s_all64;
    if (threadIdx.x == 0) s_all64 = 1;
    __syncthreads();
    int local = 1;
    for (int i = threadIdx.x; i < 4096; i += 256)
        if (t32[2 * i + 1] != 0) local = 0;
    if (!local) atomicAnd(&s_all64, 0);
    __syncthreads();
    const bool is64 = (s_all64 != 0);
    for (int i = threadIdx.x; i < NROWS; i += 256)
        g_lab[i] = is64 ? t32[2 * i] : t32[i];
}

// ---------------------------------------------------------------------------
// Row squared norms: one warp per row, coalesced float4 loads. Also warms L2
// with the full 4 MB input so the main kernel's gathers hit L2.
// ---------------------------------------------------------------------------
__global__ void sq_kernel(const float* __restrict__ x) {
    int gwarp = (blockIdx.x * blockDim.x + threadIdx.x) >> 5;
    int lane  = threadIdx.x & 31;
    if (gwarp >= NROWS) return;
    float4 v = reinterpret_cast<const float4*>(x + (size_t)gwarp * DIM)[lane];
    float s = v.x * v.x + v.y * v.y + v.z * v.z + v.w * v.w;
#pragma unroll
    for (int o = 16; o; o >>= 1) s += __shfl_xor_sync(0xffffffffu, s, o);
    if (lane == 0) g_sq[gwarp] = s;
}

__global__ void init_kernel() {
    int i = blockIdx.x * blockDim.x + threadIdx.x;
    if (i < NROWS) { g_ap2[i] = 0u; g_an2[i] = 0x7f800000u; }  // 0 / +inf
}

// ---------------------------------------------------------------------------
// Transposing tile loader: global row-major [rows][128] -> smem float4 array
// dst[k*32 + (f ^ (k&31))], where chunk f holds rows 4f..4f+3 at column k.
//  - Global: per warp, lanes span 32 consecutive k at fixed row -> 128B coalesced.
//  - STS: chunk = f ^ lane-permutation -> conflict-free per 8-lane phase.
// ---------------------------------------------------------------------------
__device__ __forceinline__ void load_tile_T(float4* __restrict__ dst,
                                            const float* __restrict__ x,
                                            int rowbase, int tid) {
#pragma unroll
    for (int i = 0; i < 16; i++) {
        int idx = tid + i * 256;     // 0..4095
        int f   = idx >> 7;          // 0..31  (row-quad)
        int k   = idx & 127;         // 0..127 (column)
        const float* p = x + (size_t)(rowbase + f * 4) * DIM + k;
        float4 v = make_float4(p[0], p[DIM], p[2 * DIM], p[3 * DIM]);
        dst[k * 32 + (f ^ (k & 31))] = v;
    }
}

// ---------------------------------------------------------------------------
// Main fused kernel: 128x128 block tile, 8x8 per thread, full K=128.
// grid = (64, JSPLIT). Per-row running max(d^2, same-label) / min(d^2, diff).
// ---------------------------------------------------------------------------
__global__ void __launch_bounds__(256, 1)
triplet_main_kernel(const float* __restrict__ x) {
    extern __shared__ float4 smem[];
    float4* A4   = smem;                 // 4096 float4 (64 KB)
    float4* B4   = smem + 4096;          // 2 x 4096 float4 (128 KB)
    float*  sqj  = (float*)(smem + 4096 + 8192);  // [2][128]
    int*    labj = (int*)(sqj + 2 * BN);          // [2][128]

    const int tid = threadIdx.x;
    const int tx  = tid & 15;
    const int ty  = tid >> 4;
    const int ibase = blockIdx.x * BM;
    const int t0    = blockIdx.y * TILES_PER;

    load_tile_T(A4, x, ibase, tid);
    load_tile_T(B4, x, t0 * BN, tid);
    if (tid < BN) {
        sqj[tid]  = g_sq[t0 * BN + tid];
        labj[tid] = g_lab[t0 * BN + tid];
    }

    float sqi[8]; int labi[8];
    float ap[8], an[8];
#pragma unroll
    for (int r = 0; r < 8; r++) {
        int row = ibase + ((r < 4) ? ty * 4 + r : 64 + ty * 4 + (r - 4));
        sqi[r]  = g_sq[row];
        labi[r] = g_lab[row];
        ap[r] = 0.0f;
        an[r] = __int_as_float(0x7f800000);
    }
    __syncthreads();

    for (int t = t0; t < t0 + TILES_PER; ++t) {
        const int buf = (t - t0) & 1;

        // Prefetch next B tile into the other buffer (overlaps with compute).
        if (t + 1 < t0 + TILES_PER) {
            const int nb = buf ^ 1;
            const int jb = (t + 1) * BN;
            load_tile_T(B4 + nb * 4096, x, jb, tid);
            if (tid < BN) {
                sqj[nb * BN + tid]  = g_sq[jb + tid];
                labj[nb * BN + tid] = g_lab[jb + tid];
            }
        }

        const float4* Bb = B4 + buf * 4096;
        float acc[8][8];
#pragma unroll
        for (int r = 0; r < 8; r++)
#pragma unroll
            for (int c = 0; c < 8; c++) acc[r][c] = 0.0f;

#pragma unroll 4
        for (int k = 0; k < DIM; ++k) {
            const int cx = k & 31;
            float4 A0 = A4[k * 32 + (ty ^ cx)];
            float4 A1 = A4[k * 32 + ((16 + ty) ^ cx)];
            float4 B0 = Bb[k * 32 + (tx ^ cx)];
            float4 B1 = Bb[k * 32 + ((16 + tx) ^ cx)];
            float a[8] = {A0.x, A0.y, A0.z, A0.w, A1.x, A1.y, A1.z, A1.w};
            float b[8] = {B0.x, B0.y, B0.z, B0.w, B1.x, B1.y, B1.z, B1.w};
#pragma unroll
            for (int r = 0; r < 8; r++)
#pragma unroll
                for (int c = 0; c < 8; c++)
                    acc[r][c] = fmaf(a[r], b[c], acc[r][c]);
        }

        // Epilogue: d^2 = sqi + sqj - 2*dot, clamp, mine on d^2 (sqrt deferred)
        float sjv[8]; int ljv[8];
#pragma unroll
        for (int c = 0; c < 8; c++) {
            int col = (c < 4) ? tx * 4 + c : 64 + tx * 4 + (c - 4);
            sjv[c] = sqj[buf * BN + col];
            ljv[c] = labj[buf * BN + col];
        }
#pragma unroll
        for (int r = 0; r < 8; r++) {
#pragma unroll
            for (int c = 0; c < 8; c++) {
                float d2 = fmaf(-2.0f, acc[r][c], sqi[r] + sjv[c]);
                d2 = fmaxf(d2, 1e-12f);
                if (labi[r] == ljv[c]) ap[r] = fmaxf(ap[r], d2);
                else                   an[r] = fminf(an[r], d2);
            }
        }
        __syncthreads();
    }

    // Reduce across the 16 tx-lanes (lanes l and l^8.. stay in 16-lane group)
#pragma unroll
    for (int o = 8; o; o >>= 1) {
#pragma unroll
        for (int r = 0; r < 8; r++) {
            ap[r] = fmaxf(ap[r], __shfl_xor_sync(0xffffffffu, ap[r], o));
            an[r] = fminf(an[r], __shfl_xor_sync(0xffffffffu, an[r], o));
        }
    }
    if (tx == 0) {
#pragma unroll
        for (int r = 0; r < 8; r++) {
            int row = ibase + ((r < 4) ? ty * 4 + r : 64 + ty * 4 + (r - 4));
            atomicMax(&g_ap2[row], __float_as_uint(ap[r]));  // all values > 0
            atomicMin(&g_an2[row], __float_as_uint(an[r]));
        }
    }
}

// ---------------------------------------------------------------------------
// Finalize: sqrt the mined d^2, margin ranking loss + precision means.
// ---------------------------------------------------------------------------
__global__ void finalize_kernel(float* __restrict__ out, int out_size) {
    __shared__ float sl[256], sp[256];
    float loss = 0.0f, prec = 0.0f;
    for (int i = threadIdx.x; i < NROWS; i += 256) {
        float dap = sqrtf(__uint_as_float(g_ap2[i]));
        float dan = sqrtf(__uint_as_float(g_an2[i]));
        loss += fmaxf(0.0f, MARGIN_F - (dan - dap));
        prec += (dan > dap) ? 1.0f : 0.0f;
    }
    sl[threadIdx.x] = loss;
    sp[threadIdx.x] = prec;
    __syncthreads();
#pragma unroll
    for (int s = 128; s > 0; s >>= 1) {
        if (threadIdx.x < s) {
            sl[threadIdx.x] += sl[threadIdx.x + s];
            sp[threadIdx.x] += sp[threadIdx.x + s];
        }
        __syncthreads();
    }
    if (threadIdx.x == 0) {
        out[0] = sl[0] / (float)NROWS;
        if (out_size > 1) out[1] = sp[0] / (float)NROWS;
    }
}

// ---------------------------------------------------------------------------
extern "C" void kernel_launch(void* const* d_in, const int* in_sizes, int n_in,
                              void* d_out, int out_size) {
    const float* x   = (const float*)d_in[0];
    const int*   t32 = (const int*)d_in[1];  // raw view; prep normalizes dtype
    (void)in_sizes; (void)n_in;

    const int smem_bytes = (4096 + 8192) * 16 + 2 * BN * 4 + 2 * BN * 4;
    cudaFuncSetAttribute(triplet_main_kernel,
                         cudaFuncAttributeMaxDynamicSharedMemorySize, smem_bytes);

    prep_labels_kernel<<<1, 256>>>(t32);
    sq_kernel<<<NROWS * 32 / 256, 256>>>(x);
    init_kernel<<<NROWS / 256, 256>>>();
    triplet_main_kernel<<<dim3(NROWS / BM, JSPLIT), 256, smem_bytes>>>(x);
    finalize_kernel<<<1, 256>>>((float*)d_out, out_size);
}

// round 3
// speedup vs baseline: 2.0706x; 2.0706x over previous
#include <cuda_runtime.h>
#include <cstdint>

#define NROWS 8192
#define DIM   128
#define BM    128
#define BN    128
#define NTILES (NROWS / BN)                  // 64
#define NUNITS (NTILES * (NTILES + 1) / 2)   // 2080 triangle tile-pairs
#define GRID_MAIN 148
#define RSTRIDE   130                        // floats per smem tile row (conflict-free LDS.64)
#define RSTRIDE64 65
#define TILE_F (BM * RSTRIDE)                // 16640 floats per tile
#define MARGIN_F 0.3f

typedef unsigned long long u64;

// Scratch (device globals; no allocations allowed)
__device__ unsigned int g_ap2[NROWS];   // max same-label d^2 (float bits)
__device__ unsigned int g_an2[NROWS];   // min diff-label d^2 (float bits)
__device__ float        g_sq[NROWS];    // ||x_i||^2
__device__ int          g_lab[NROWS];   // normalized labels (int32)

// ---------------------------------------------------------------------------
// Small helpers: cp.async + smem addressing
// ---------------------------------------------------------------------------
__device__ __forceinline__ unsigned smem_u32(const void* p) {
    unsigned r;
    asm("{ .reg .u64 t; cvta.to.shared.u64 t, %1; cvt.u32.u64 %0, t; }"
        : "=r"(r) : "l"(p));
    return r;
}
__device__ __forceinline__ void cp8(unsigned dst, const void* src) {
    asm volatile("cp.async.ca.shared.global [%0], [%1], 8;" :: "r"(dst), "l"(src));
}
__device__ __forceinline__ void cp4(unsigned dst, const void* src) {
    asm volatile("cp.async.ca.shared.global [%0], [%1], 4;" :: "r"(dst), "l"(src));
}
__device__ __forceinline__ void cp_commit() { asm volatile("cp.async.commit_group;"); }
__device__ __forceinline__ void cp_wait1()  { asm volatile("cp.async.wait_group 1;" ::: "memory"); }
__device__ __forceinline__ void cp_wait0()  { asm volatile("cp.async.wait_group 0;" ::: "memory"); }

// ---------------------------------------------------------------------------
// Label prep: targets may be int64 or int32; normalize to int32.
// ---------------------------------------------------------------------------
__global__ void prep_labels_kernel(const int* __restrict__ t32) {
    __shared__ int s_all64;
    if (threadIdx.x == 0) s_all64 = 1;
    __syncthreads();
    int local = 1;
    for (int i = threadIdx.x; i < 4096; i += 256)
        if (t32[2 * i + 1] != 0) local = 0;
    if (!local) atomicAnd(&s_all64, 0);
    __syncthreads();
    const bool is64 = (s_all64 != 0);
    for (int i = threadIdx.x; i < NROWS; i += 256)
        g_lab[i] = is64 ? t32[2 * i] : t32[i];
}

// ---------------------------------------------------------------------------
// Row squared norms.
// ---------------------------------------------------------------------------
__global__ void sq_kernel(const float* __restrict__ x) {
    int gwarp = (blockIdx.x * blockDim.x + threadIdx.x) >> 5;
    int lane  = threadIdx.x & 31;
    if (gwarp >= NROWS) return;
    float4 v = reinterpret_cast<const float4*>(x + (size_t)gwarp * DIM)[lane];
    float s = v.x * v.x + v.y * v.y + v.z * v.z + v.w * v.w;
#pragma unroll
    for (int o = 16; o; o >>= 1) s += __shfl_xor_sync(0xffffffffu, s, o);
    if (lane == 0) g_sq[gwarp] = s;
}

__global__ void init_kernel() {
    int i = blockIdx.x * blockDim.x + threadIdx.x;
    if (i < NROWS) { g_ap2[i] = 0u; g_an2[i] = 0x7f800000u; }  // 0 / +inf
}

// ---------------------------------------------------------------------------
// Tile loaders: global row-major [rows][128] -> smem row-major, stride 130.
// Async version (cp.async, 8B chunks, 8B-aligned for odd rows) and plain.
// ---------------------------------------------------------------------------
__device__ __forceinline__ void load_tile_async(unsigned dst_u32,
                                                const float* __restrict__ x,
                                                int rowbase, int tid) {
#pragma unroll
    for (int i = 0; i < 16; i++) {
        int idx = tid + i * 256;      // 0..4095
        int row = idx >> 5;           // 0..127
        int q   = idx & 31;           // float4 chunk 0..31
        const float* src = x + (size_t)(rowbase + row) * DIM + q * 4;
        unsigned d = dst_u32 + (unsigned)(row * RSTRIDE + q * 4) * 4u;
        cp8(d, src);
        cp8(d + 8, src + 2);
    }
}

__device__ __forceinline__ void load_tile_plain(float* __restrict__ dst,
                                                const float* __restrict__ x,
                                                int rowbase, int tid) {
#pragma unroll
    for (int i = 0; i < 16; i++) {
        int idx = tid + i * 256;
        int row = idx >> 5;
        int q   = idx & 31;
        float4 v = reinterpret_cast<const float4*>(x + (size_t)(rowbase + row) * DIM)[q];
        float2* d = reinterpret_cast<float2*>(dst + row * RSTRIDE + q * 4);
        d[0] = make_float2(v.x, v.y);
        d[1] = make_float2(v.z, v.w);
    }
}

// ---------------------------------------------------------------------------
// Main persistent kernel: triangle tile-pairs (ti <= tj), packed f32x2 FMA.
// Each 128x128 tile updates BOTH row-side (i) and col-side (j) mining
// (symmetry: dist[i,j] == dist[j,i]); max/min atomics are idempotent so the
// diagonal tile's double coverage is harmless.
// ---------------------------------------------------------------------------
__global__ void __launch_bounds__(256, 1)
triplet_main_kernel(const float* __restrict__ x) {
    extern __shared__ float smem[];
    float* As    = smem;                       // [128][130]
    float* Bs0   = smem + TILE_F;              // [128][130]
    float* Bs1   = smem + 2 * TILE_F;          // [128][130]
    float* sqis  = smem + 3 * TILE_F;          // [128]
    int*   labis = (int*)(sqis + BM);          // [128]
    float* sqjs  = (float*)(labis + BM);       // [2][128]
    int*   labjs = (int*)(sqjs + 2 * BN);      // [2][128]
    float* colAp = (float*)(labjs + 2 * BN);   // [8][128]
    float* colAn = colAp + 8 * BN;             // [8][128]

    const int tid = threadIdx.x;
    const int tx = tid & 15, ty = tid >> 4;

    const unsigned As_u   = smem_u32(As);
    const unsigned Bs0_u  = smem_u32(Bs0);
    const unsigned Bs1_u  = smem_u32(Bs1);
    const unsigned sqis_u = smem_u32(sqis);
    const unsigned labis_u = smem_u32(labis);
    const unsigned sqjs_u = smem_u32(sqjs);
    const unsigned labjs_u = smem_u32(labjs);

    // Static contiguous unit range for this CTA (row-major triangle order
    // keeps consecutive units on the same ti -> A tile reuse).
    int u0 = (int)((long long)blockIdx.x * NUNITS / gridDim.x);
    int u1 = (int)((long long)(blockIdx.x + 1) * NUNITS / gridDim.x);
    if (u0 >= u1) return;

    int ti = 0, rem = u0;
    while (rem >= NTILES - ti) { rem -= NTILES - ti; ti++; }
    int tj = ti + rem;

    // Prologue group: A tile + A meta + B(u0) tile + B meta
    load_tile_async(As_u, x, ti * BM, tid);
    load_tile_async(Bs0_u, x, tj * BN, tid);
    if (tid < BM) {
        cp4(sqis_u + tid * 4,  g_sq  + ti * BM + tid);
        cp4(labis_u + tid * 4, g_lab + ti * BM + tid);
        cp4(sqjs_u + tid * 4,  g_sq  + tj * BN + tid);
        cp4(labjs_u + tid * 4, g_lab + tj * BN + tid);
    }
    cp_commit();

    int curti = ti;

    for (int u = u0; u < u1; ++u) {
        const int buf = (u - u0) & 1;
        int nti = ti, ntj = tj + 1;
        if (ntj == NTILES) { nti = ti + 1; ntj = nti; }
        const bool has_next = (u + 1 < u1);

        // Prefetch next B tile (async; lands while we compute on current).
        if (has_next) {
            load_tile_async(buf ? Bs0_u : Bs1_u, x, ntj * BN, tid);
            if (tid < BN) {
                cp4(sqjs_u + ((buf ^ 1) * BN + tid) * 4,  g_sq  + ntj * BN + tid);
                cp4(labjs_u + ((buf ^ 1) * BN + tid) * 4, g_lab + ntj * BN + tid);
            }
            cp_commit();
            cp_wait1();   // current buffer's group has completed
        } else {
            cp_wait0();
        }
        __syncthreads();

        // ---- GEMM: acc[r][c] packed (even-k, odd-k) partial sums ----
        u64 acc[8][8];
#pragma unroll
        for (int r = 0; r < 8; r++)
#pragma unroll
            for (int c = 0; c < 8; c++) acc[r][c] = 0ull;

        const u64* A64 = reinterpret_cast<const u64*>(As) + ty * RSTRIDE64;
        const u64* B64 = reinterpret_cast<const u64*>(buf ? Bs1 : Bs0) + tx * RSTRIDE64;

#pragma unroll 2
        for (int k = 0; k < DIM / 2; ++k) {
            u64 a2[8], b2[8];
#pragma unroll
            for (int r = 0; r < 8; r++) a2[r] = A64[k + r * (16 * RSTRIDE64)];
#pragma unroll
            for (int c = 0; c < 8; c++) b2[c] = B64[k + c * (16 * RSTRIDE64)];
#pragma unroll
            for (int r = 0; r < 8; r++)
#pragma unroll
                for (int c = 0; c < 8; c++)
                    asm("fma.rn.f32x2 %0, %1, %2, %0;"
                        : "+l"(acc[r][c]) : "l"(a2[r]), "l"(b2[c]));
        }

        // ---- Epilogue: d^2 mining (row side + col side) ----
        float sjv[8]; int ljv[8];
#pragma unroll
        for (int c = 0; c < 8; c++) {
            sjv[c] = sqjs[buf * BN + tx + 16 * c];
            ljv[c] = labjs[buf * BN + tx + 16 * c];
        }
        float ap[8], an[8], apc[8], anc[8];
#pragma unroll
        for (int i = 0; i < 8; i++) {
            ap[i] = 0.0f;  an[i] = __int_as_float(0x7f800000);
            apc[i] = 0.0f; anc[i] = __int_as_float(0x7f800000);
        }
#pragma unroll
        for (int r = 0; r < 8; r++) {
            float si = sqis[ty + 16 * r];
            int   li = labis[ty + 16 * r];
#pragma unroll
            for (int c = 0; c < 8; c++) {
                float2 p = *reinterpret_cast<float2*>(&acc[r][c]);
                float d2 = fmaf(-2.0f, p.x + p.y, si + sjv[c]);
                d2 = fmaxf(d2, 1e-12f);
                if (li == ljv[c]) { ap[r] = fmaxf(ap[r], d2); apc[c] = fmaxf(apc[c], d2); }
                else              { an[r] = fminf(an[r], d2); anc[c] = fminf(anc[c], d2); }
            }
        }

        // Row side: reduce over the 16 tx-lanes (lanes 0-15 / 16-31 of a warp
        // hold the same rows), then atomics. Values > 0 => uint order == float order.
#pragma unroll
        for (int o = 8; o; o >>= 1)
#pragma unroll
            for (int r = 0; r < 8; r++) {
                ap[r] = fmaxf(ap[r], __shfl_xor_sync(0xffffffffu, ap[r], o));
                an[r] = fminf(an[r], __shfl_xor_sync(0xffffffffu, an[r], o));
            }
        if (tx == 0) {
#pragma unroll
            for (int r = 0; r < 8; r++) {
                int row = ti * BM + ty + 16 * r;
                atomicMax(&g_ap2[row], __float_as_uint(ap[r]));
                atomicMin(&g_an2[row], __float_as_uint(an[r]));
            }
        }

        // Col side: fold the ty-pair within each warp, stage per-warp partials
        // in smem, combine across 8 warps, atomics to g[tj..].
#pragma unroll
        for (int c = 0; c < 8; c++) {
            apc[c] = fmaxf(apc[c], __shfl_xor_sync(0xffffffffu, apc[c], 16));
            anc[c] = fminf(anc[c], __shfl_xor_sync(0xffffffffu, anc[c], 16));
        }
        if (((tid >> 4) & 1) == 0) {
            int w = tid >> 5;
#pragma unroll
            for (int c = 0; c < 8; c++) {
                colAp[w * BN + tx + 16 * c] = apc[c];
                colAn[w * BN + tx + 16 * c] = anc[c];
            }
        }
        __syncthreads();
        if (tid < BN) {
            float ca = colAp[tid], cn = colAn[tid];
#pragma unroll
            for (int w = 1; w < 8; w++) {
                ca = fmaxf(ca, colAp[w * BN + tid]);
                cn = fminf(cn, colAn[w * BN + tid]);
            }
            atomicMax(&g_ap2[tj * BN + tid], __float_as_uint(ca));
            atomicMin(&g_an2[tj * BN + tid], __float_as_uint(cn));
        }
        __syncthreads();   // colAp/colAn reusable; As safe to overwrite; Bs swap safe

        // A tile changes (rare): synchronous reload.
        if (has_next && nti != curti) {
            load_tile_plain(As, x, nti * BM, tid);
            if (tid < BM) {
                sqis[tid]  = g_sq[nti * BM + tid];
                labis[tid] = g_lab[nti * BM + tid];
            }
            curti = nti;
            __syncthreads();
        }
        ti = nti; tj = ntj;
    }
}

// ---------------------------------------------------------------------------
// Finalize: sqrt the mined d^2, margin ranking loss + precision means.
// ---------------------------------------------------------------------------
__global__ void finalize_kernel(float* __restrict__ out, int out_size) {
    __shared__ float sl[256], sp[256];
    float loss = 0.0f, prec = 0.0f;
    for (int i = threadIdx.x; i < NROWS; i += 256) {
        float dap = sqrtf(__uint_as_float(g_ap2[i]));
        float dan = sqrtf(__uint_as_float(g_an2[i]));
        loss += fmaxf(0.0f, MARGIN_F - (dan - dap));
        prec += (dan > dap) ? 1.0f : 0.0f;
    }
    sl[threadIdx.x] = loss;
    sp[threadIdx.x] = prec;
    __syncthreads();
#pragma unroll
    for (int s = 128; s > 0; s >>= 1) {
        if (threadIdx.x < s) {
            sl[threadIdx.x] += sl[threadIdx.x + s];
            sp[threadIdx.x] += sp[threadIdx.x + s];
        }
        __syncthreads();
    }
    if (threadIdx.x == 0) {
        out[0] = sl[0] / (float)NROWS;
        if (out_size > 1) out[1] = sp[0] / (float)NROWS;
    }
}

// ---------------------------------------------------------------------------
extern "C" void kernel_launch(void* const* d_in, const int* in_sizes, int n_in,
                              void* d_out, int out_size) {
    const float* x   = (const float*)d_in[0];
    const int*   t32 = (const int*)d_in[1];
    (void)in_sizes; (void)n_in;

    const int smem_bytes =
        (3 * TILE_F + BM /*sqis*/ + BM /*labis*/ + 2 * BN /*sqjs*/ +
         2 * BN /*labjs*/ + 8 * BN /*colAp*/ + 8 * BN /*colAn*/) * 4;
    cudaFuncSetAttribute(triplet_main_kernel,
                         cudaFuncAttributeMaxDynamicSharedMemorySize, smem_bytes);

    prep_labels_kernel<<<1, 256>>>(t32);
    sq_kernel<<<NROWS * 32 / 256, 256>>>(x);
    init_kernel<<<NROWS / 256, 256>>>();
    triplet_main_kernel<<<GRID_MAIN, 256, smem_bytes>>>(x);
    finalize_kernel<<<1, 256>>>((float*)d_out, out_size);
}

// round 4
// speedup vs baseline: 2.0711x; 1.0003x over previous
#include <cuda_runtime.h>
#include <cstdint>

#define NROWS 8192
#define DIM   128
#define BM    128
#define BN    128
#define NTILES (NROWS / BN)                  // 64
#define NUNITS (NTILES * (NTILES + 1) / 2)   // 2080 triangle tile-pairs
#define GRID_MAIN 148
#define RSTRIDE   130                        // floats per smem tile row (conflict-free LDS.64)
#define RSTRIDE64 65
#define TILE_F (BM * RSTRIDE)                // 16640 floats per tile
#define MARGIN_F 0.3f

typedef unsigned long long u64;

// Scratch (device globals; no allocations allowed)
__device__ unsigned int g_ap2[NROWS];   // max same-label d^2 (float bits)
__device__ unsigned int g_an2[NROWS];   // min diff-label d^2 (float bits)
__device__ float        g_sq[NROWS];    // ||x_i||^2
__device__ int          g_lab[NROWS];   // normalized labels (int32)

// ---------------------------------------------------------------------------
// Small helpers: cp.async + smem addressing
// ---------------------------------------------------------------------------
__device__ __forceinline__ unsigned smem_u32(const void* p) {
    unsigned r;
    asm("{ .reg .u64 t; cvta.to.shared.u64 t, %1; cvt.u32.u64 %0, t; }"
        : "=r"(r) : "l"(p));
    return r;
}
__device__ __forceinline__ void cp8(unsigned dst, const void* src) {
    asm volatile("cp.async.ca.shared.global [%0], [%1], 8;" :: "r"(dst), "l"(src));
}
__device__ __forceinline__ void cp4(unsigned dst, const void* src) {
    asm volatile("cp.async.ca.shared.global [%0], [%1], 4;" :: "r"(dst), "l"(src));
}
__device__ __forceinline__ void cp_commit() { asm volatile("cp.async.commit_group;"); }
__device__ __forceinline__ void cp_wait1()  { asm volatile("cp.async.wait_group 1;" ::: "memory"); }
__device__ __forceinline__ void cp_wait0()  { asm volatile("cp.async.wait_group 0;" ::: "memory"); }

// ---------------------------------------------------------------------------
// Label prep: targets may be int64 or int32; normalize to int32.
// ---------------------------------------------------------------------------
__global__ void prep_labels_kernel(const int* __restrict__ t32) {
    __shared__ int s_all64;
    if (threadIdx.x == 0) s_all64 = 1;
    __syncthreads();
    int local = 1;
    for (int i = threadIdx.x; i < 4096; i += 256)
        if (t32[2 * i + 1] != 0) local = 0;
    if (!local) atomicAnd(&s_all64, 0);
    __syncthreads();
    const bool is64 = (s_all64 != 0);
    for (int i = threadIdx.x; i < NROWS; i += 256)
        g_lab[i] = is64 ? t32[2 * i] : t32[i];
}

// ---------------------------------------------------------------------------
// Row squared norms.
// ---------------------------------------------------------------------------
__global__ void sq_kernel(const float* __restrict__ x) {
    int gwarp = (blockIdx.x * blockDim.x + threadIdx.x) >> 5;
    int lane  = threadIdx.x & 31;
    if (gwarp >= NROWS) return;
    float4 v = reinterpret_cast<const float4*>(x + (size_t)gwarp * DIM)[lane];
    float s = v.x * v.x + v.y * v.y + v.z * v.z + v.w * v.w;
#pragma unroll
    for (int o = 16; o; o >>= 1) s += __shfl_xor_sync(0xffffffffu, s, o);
    if (lane == 0) g_sq[gwarp] = s;
}

__global__ void init_kernel() {
    int i = blockIdx.x * blockDim.x + threadIdx.x;
    if (i < NROWS) { g_ap2[i] = 0u; g_an2[i] = 0x7f800000u; }  // 0 / +inf
}

// ---------------------------------------------------------------------------
// Tile loaders: global row-major [rows][128] -> smem row-major, stride 130.
// Async version (cp.async, 8B chunks, 8B-aligned for odd rows) and plain.
// ---------------------------------------------------------------------------
__device__ __forceinline__ void load_tile_async(unsigned dst_u32,
                                                const float* __restrict__ x,
                                                int rowbase, int tid) {
#pragma unroll
    for (int i = 0; i < 16; i++) {
        int idx = tid + i * 256;      // 0..4095
        int row = idx >> 5;           // 0..127
        int q   = idx & 31;           // float4 chunk 0..31
        const float* src = x + (size_t)(rowbase + row) * DIM + q * 4;
        unsigned d = dst_u32 + (unsigned)(row * RSTRIDE + q * 4) * 4u;
        cp8(d, src);
        cp8(d + 8, src + 2);
    }
}

__device__ __forceinline__ void load_tile_plain(float* __restrict__ dst,
                                                const float* __restrict__ x,
                                                int rowbase, int tid) {
#pragma unroll
    for (int i = 0; i < 16; i++) {
        int idx = tid + i * 256;
        int row = idx >> 5;
        int q   = idx & 31;
        float4 v = reinterpret_cast<const float4*>(x + (size_t)(rowbase + row) * DIM)[q];
        float2* d = reinterpret_cast<float2*>(dst + row * RSTRIDE + q * 4);
        d[0] = make_float2(v.x, v.y);
        d[1] = make_float2(v.z, v.w);
    }
}

// ---------------------------------------------------------------------------
// Main persistent kernel: triangle tile-pairs (ti <= tj), packed f32x2 FMA.
// Each 128x128 tile updates BOTH row-side (i) and col-side (j) mining
// (symmetry: dist[i,j] == dist[j,i]); max/min atomics are idempotent so the
// diagonal tile's double coverage is harmless.
// ---------------------------------------------------------------------------
__global__ void __launch_bounds__(256, 1)
triplet_main_kernel(const float* __restrict__ x) {
    extern __shared__ float smem[];
    float* As    = smem;                       // [128][130]
    float* Bs0   = smem + TILE_F;              // [128][130]
    float* Bs1   = smem + 2 * TILE_F;          // [128][130]
    float* sqis  = smem + 3 * TILE_F;          // [128]
    int*   labis = (int*)(sqis + BM);          // [128]
    float* sqjs  = (float*)(labis + BM);       // [2][128]
    int*   labjs = (int*)(sqjs + 2 * BN);      // [2][128]
    float* colAp = (float*)(labjs + 2 * BN);   // [8][128]
    float* colAn = colAp + 8 * BN;             // [8][128]

    const int tid = threadIdx.x;
    const int tx = tid & 15, ty = tid >> 4;

    const unsigned As_u   = smem_u32(As);
    const unsigned Bs0_u  = smem_u32(Bs0);
    const unsigned Bs1_u  = smem_u32(Bs1);
    const unsigned sqis_u = smem_u32(sqis);
    const unsigned labis_u = smem_u32(labis);
    const unsigned sqjs_u = smem_u32(sqjs);
    const unsigned labjs_u = smem_u32(labjs);

    // Static contiguous unit range for this CTA (row-major triangle order
    // keeps consecutive units on the same ti -> A tile reuse).
    int u0 = (int)((long long)blockIdx.x * NUNITS / gridDim.x);
    int u1 = (int)((long long)(blockIdx.x + 1) * NUNITS / gridDim.x);
    if (u0 >= u1) return;

    int ti = 0, rem = u0;
    while (rem >= NTILES - ti) { rem -= NTILES - ti; ti++; }
    int tj = ti + rem;

    // Prologue group: A tile + A meta + B(u0) tile + B meta
    load_tile_async(As_u, x, ti * BM, tid);
    load_tile_async(Bs0_u, x, tj * BN, tid);
    if (tid < BM) {
        cp4(sqis_u + tid * 4,  g_sq  + ti * BM + tid);
        cp4(labis_u + tid * 4, g_lab + ti * BM + tid);
        cp4(sqjs_u + tid * 4,  g_sq  + tj * BN + tid);
        cp4(labjs_u + tid * 4, g_lab + tj * BN + tid);
    }
    cp_commit();

    int curti = ti;

    for (int u = u0; u < u1; ++u) {
        const int buf = (u - u0) & 1;
        int nti = ti, ntj = tj + 1;
        if (ntj == NTILES) { nti = ti + 1; ntj = nti; }
        const bool has_next = (u + 1 < u1);

        // Prefetch next B tile (async; lands while we compute on current).
        if (has_next) {
            load_tile_async(buf ? Bs0_u : Bs1_u, x, ntj * BN, tid);
            if (tid < BN) {
                cp4(sqjs_u + ((buf ^ 1) * BN + tid) * 4,  g_sq  + ntj * BN + tid);
                cp4(labjs_u + ((buf ^ 1) * BN + tid) * 4, g_lab + ntj * BN + tid);
            }
            cp_commit();
            cp_wait1();   // current buffer's group has completed
        } else {
            cp_wait0();
        }
        __syncthreads();

        // ---- GEMM: acc[r][c] packed (even-k, odd-k) partial sums ----
        u64 acc[8][8];
#pragma unroll
        for (int r = 0; r < 8; r++)
#pragma unroll
            for (int c = 0; c < 8; c++) acc[r][c] = 0ull;

        const u64* A64 = reinterpret_cast<const u64*>(As) + ty * RSTRIDE64;
        const u64* B64 = reinterpret_cast<const u64*>(buf ? Bs1 : Bs0) + tx * RSTRIDE64;

#pragma unroll 2
        for (int k = 0; k < DIM / 2; ++k) {
            u64 a2[8], b2[8];
#pragma unroll
            for (int r = 0; r < 8; r++) a2[r] = A64[k + r * (16 * RSTRIDE64)];
#pragma unroll
            for (int c = 0; c < 8; c++) b2[c] = B64[k + c * (16 * RSTRIDE64)];
#pragma unroll
            for (int r = 0; r < 8; r++)
#pragma unroll
                for (int c = 0; c < 8; c++)
                    asm("fma.rn.f32x2 %0, %1, %2, %0;"
                        : "+l"(acc[r][c]) : "l"(a2[r]), "l"(b2[c]));
        }

        // ---- Epilogue: d^2 mining (row side + col side) ----
        float sjv[8]; int ljv[8];
#pragma unroll
        for (int c = 0; c < 8; c++) {
            sjv[c] = sqjs[buf * BN + tx + 16 * c];
            ljv[c] = labjs[buf * BN + tx + 16 * c];
        }
        float ap[8], an[8], apc[8], anc[8];
#pragma unroll
        for (int i = 0; i < 8; i++) {
            ap[i] = 0.0f;  an[i] = __int_as_float(0x7f800000);
            apc[i] = 0.0f; anc[i] = __int_as_float(0x7f800000);
        }
#pragma unroll
        for (int r = 0; r < 8; r++) {
            float si = sqis[ty + 16 * r];
            int   li = labis[ty + 16 * r];
#pragma unroll
            for (int c = 0; c < 8; c++) {
                float2 p = *reinterpret_cast<float2*>(&acc[r][c]);
                float d2 = fmaf(-2.0f, p.x + p.y, si + sjv[c]);
                d2 = fmaxf(d2, 1e-12f);
                if (li == ljv[c]) { ap[r] = fmaxf(ap[r], d2); apc[c] = fmaxf(apc[c], d2); }
                else              { an[r] = fminf(an[r], d2); anc[c] = fminf(anc[c], d2); }
            }
        }

        // Row side: reduce over the 16 tx-lanes (lanes 0-15 / 16-31 of a warp
        // hold the same rows), then atomics. Values > 0 => uint order == float order.
#pragma unroll
        for (int o = 8; o; o >>= 1)
#pragma unroll
            for (int r = 0; r < 8; r++) {
                ap[r] = fmaxf(ap[r], __shfl_xor_sync(0xffffffffu, ap[r], o));
                an[r] = fminf(an[r], __shfl_xor_sync(0xffffffffu, an[r], o));
            }
        if (tx == 0) {
#pragma unroll
            for (int r = 0; r < 8; r++) {
                int row = ti * BM + ty + 16 * r;
                atomicMax(&g_ap2[row], __float_as_uint(ap[r]));
                atomicMin(&g_an2[row], __float_as_uint(an[r]));
            }
        }

        // Col side: fold the ty-pair within each warp, stage per-warp partials
        // in smem, combine across 8 warps, atomics to g[tj..].
#pragma unroll
        for (int c = 0; c < 8; c++) {
            apc[c] = fmaxf(apc[c], __shfl_xor_sync(0xffffffffu, apc[c], 16));
            anc[c] = fminf(anc[c], __shfl_xor_sync(0xffffffffu, anc[c], 16));
        }
        if (((tid >> 4) & 1) == 0) {
            int w = tid >> 5;
#pragma unroll
            for (int c = 0; c < 8; c++) {
                colAp[w * BN + tx + 16 * c] = apc[c];
                colAn[w * BN + tx + 16 * c] = anc[c];
            }
        }
        __syncthreads();
        if (tid < BN) {
            float ca = colAp[tid], cn = colAn[tid];
#pragma unroll
            for (int w = 1; w < 8; w++) {
                ca = fmaxf(ca, colAp[w * BN + tid]);
                cn = fminf(cn, colAn[w * BN + tid]);
            }
            atomicMax(&g_ap2[tj * BN + tid], __float_as_uint(ca));
            atomicMin(&g_an2[tj * BN + tid], __float_as_uint(cn));
        }
        __syncthreads();   // colAp/colAn reusable; As safe to overwrite; Bs swap safe

        // A tile changes (rare): synchronous reload.
        if (has_next && nti != curti) {
            load_tile_plain(As, x, nti * BM, tid);
            if (tid < BM) {
                sqis[tid]  = g_sq[nti * BM + tid];
                labis[tid] = g_lab[nti * BM + tid];
            }
            curti = nti;
            __syncthreads();
        }
        ti = nti; tj = ntj;
    }
}

// ---------------------------------------------------------------------------
// Finalize: sqrt the mined d^2, margin ranking loss + precision means.
// ---------------------------------------------------------------------------
__global__ void finalize_kernel(float* __restrict__ out, int out_size) {
    __shared__ float sl[256], sp[256];
    float loss = 0.0f, prec = 0.0f;
    for (int i = threadIdx.x; i < NROWS; i += 256) {
        float dap = sqrtf(__uint_as_float(g_ap2[i]));
        float dan = sqrtf(__uint_as_float(g_an2[i]));
        loss += fmaxf(0.0f, MARGIN_F - (dan - dap));
        prec += (dan > dap) ? 1.0f : 0.0f;
    }
    sl[threadIdx.x] = loss;
    sp[threadIdx.x] = prec;
    __syncthreads();
#pragma unroll
    for (int s = 128; s > 0; s >>= 1) {
        if (threadIdx.x < s) {
            sl[threadIdx.x] += sl[threadIdx.x + s];
            sp[threadIdx.x] += sp[threadIdx.x + s];
        }
        __syncthreads();
    }
    if (threadIdx.x == 0) {
        out[0] = sl[0] / (float)NROWS;
        if (out_size > 1) out[1] = sp[0] / (float)NROWS;
    }
}

// ---------------------------------------------------------------------------
extern "C" void kernel_launch(void* const* d_in, const int* in_sizes, int n_in,
                              void* d_out, int out_size) {
    const float* x   = (const float*)d_in[0];
    const int*   t32 = (const int*)d_in[1];
    (void)in_sizes; (void)n_in;

    const int smem_bytes =
        (3 * TILE_F + BM /*sqis*/ + BM /*labis*/ + 2 * BN /*sqjs*/ +
         2 * BN /*labjs*/ + 8 * BN /*colAp*/ + 8 * BN /*colAn*/) * 4;
    cudaFuncSetAttribute(triplet_main_kernel,
                         cudaFuncAttributeMaxDynamicSharedMemorySize, smem_bytes);

    prep_labels_kernel<<<1, 256>>>(t32);
    sq_kernel<<<NROWS * 32 / 256, 256>>>(x);
    init_kernel<<<NROWS / 256, 256>>>();
    triplet_main_kernel<<<GRID_MAIN, 256, smem_bytes>>>(x);
    finalize_kernel<<<1, 256>>>((float*)d_out, out_size);
}

// round 5
// speedup vs baseline: 2.0795x; 1.0041x over previous
#include <cuda_runtime.h>
#include <cstdint>

#define NROWS 8192
#define DIM   128
#define BM    128
#define BN    128
#define NTILES (NROWS / BN)                  // 64
#define NUNITS (NTILES * (NTILES + 1) / 2)   // 2080 triangle tile-pairs
#define GRID_MAIN 148
#define RSTRIDE   130                        // floats per smem tile row (conflict-free LDS.64)
#define RSTRIDE64 65
#define TILE_F (BM * RSTRIDE)                // 16640 floats per tile
#define MARGIN_F 0.3f

typedef unsigned long long u64;

// Scratch (device globals; no allocations allowed)
__device__ unsigned int g_ap2[NROWS];   // max same-label d^2 (float bits)
__device__ unsigned int g_an2[NROWS];   // min diff-label d^2 (float bits)
__device__ float        g_sq[NROWS];    // ||x_i||^2
__device__ int          g_lab[NROWS];   // normalized labels (int32)

// ---------------------------------------------------------------------------
// Small helpers: cp.async + smem addressing
// ---------------------------------------------------------------------------
__device__ __forceinline__ unsigned smem_u32(const void* p) {
    unsigned r;
    asm("{ .reg .u64 t; cvta.to.shared.u64 t, %1; cvt.u32.u64 %0, t; }"
        : "=r"(r) : "l"(p));
    return r;
}
__device__ __forceinline__ void cp8(unsigned dst, const void* src) {
    asm volatile("cp.async.ca.shared.global [%0], [%1], 8;" :: "r"(dst), "l"(src));
}
__device__ __forceinline__ void cp4(unsigned dst, const void* src) {
    asm volatile("cp.async.ca.shared.global [%0], [%1], 4;" :: "r"(dst), "l"(src));
}
__device__ __forceinline__ void cp_commit() { asm volatile("cp.async.commit_group;"); }
__device__ __forceinline__ void cp_wait1()  { asm volatile("cp.async.wait_group 1;" ::: "memory"); }
__device__ __forceinline__ void cp_wait0()  { asm volatile("cp.async.wait_group 0;" ::: "memory"); }

// ---------------------------------------------------------------------------
// Label prep: targets may be int64 or int32; normalize to int32.
// ---------------------------------------------------------------------------
__global__ void prep_labels_kernel(const int* __restrict__ t32) {
    __shared__ int s_all64;
    if (threadIdx.x == 0) s_all64 = 1;
    __syncthreads();
    int local = 1;
    for (int i = threadIdx.x; i < 4096; i += 256)
        if (t32[2 * i + 1] != 0) local = 0;
    if (!local) atomicAnd(&s_all64, 0);
    __syncthreads();
    const bool is64 = (s_all64 != 0);
    for (int i = threadIdx.x; i < NROWS; i += 256)
        g_lab[i] = is64 ? t32[2 * i] : t32[i];
}

// ---------------------------------------------------------------------------
// Row squared norms.
// ---------------------------------------------------------------------------
__global__ void sq_kernel(const float* __restrict__ x) {
    int gwarp = (blockIdx.x * blockDim.x + threadIdx.x) >> 5;
    int lane  = threadIdx.x & 31;
    if (gwarp >= NROWS) return;
    float4 v = reinterpret_cast<const float4*>(x + (size_t)gwarp * DIM)[lane];
    float s = v.x * v.x + v.y * v.y + v.z * v.z + v.w * v.w;
#pragma unroll
    for (int o = 16; o; o >>= 1) s += __shfl_xor_sync(0xffffffffu, s, o);
    if (lane == 0) g_sq[gwarp] = s;
}

__global__ void init_kernel() {
    int i = blockIdx.x * blockDim.x + threadIdx.x;
    if (i < NROWS) { g_ap2[i] = 0u; g_an2[i] = 0x7f800000u; }  // 0 / +inf
}

// ---------------------------------------------------------------------------
// Tile loaders: global row-major [rows][128] -> smem row-major, stride 130.
// Async version (cp.async, 8B chunks, 8B-aligned for odd rows) and plain.
// ---------------------------------------------------------------------------
__device__ __forceinline__ void load_tile_async(unsigned dst_u32,
                                                const float* __restrict__ x,
                                                int rowbase, int tid) {
#pragma unroll
    for (int i = 0; i < 16; i++) {
        int idx = tid + i * 256;      // 0..4095
        int row = idx >> 5;           // 0..127
        int q   = idx & 31;           // float4 chunk 0..31
        const float* src = x + (size_t)(rowbase + row) * DIM + q * 4;
        unsigned d = dst_u32 + (unsigned)(row * RSTRIDE + q * 4) * 4u;
        cp8(d, src);
        cp8(d + 8, src + 2);
    }
}

__device__ __forceinline__ void load_tile_plain(float* __restrict__ dst,
                                                const float* __restrict__ x,
                                                int rowbase, int tid) {
#pragma unroll
    for (int i = 0; i < 16; i++) {
        int idx = tid + i * 256;
        int row = idx >> 5;
        int q   = idx & 31;
        float4 v = reinterpret_cast<const float4*>(x + (size_t)(rowbase + row) * DIM)[q];
        float2* d = reinterpret_cast<float2*>(dst + row * RSTRIDE + q * 4);
        d[0] = make_float2(v.x, v.y);
        d[1] = make_float2(v.z, v.w);
    }
}

// ---------------------------------------------------------------------------
// Main persistent kernel: triangle tile-pairs (ti <= tj), packed f32x2 FMA.
// Each 128x128 tile updates BOTH row-side (i) and col-side (j) mining
// (symmetry: dist[i,j] == dist[j,i]); max/min atomics are idempotent so the
// diagonal tile's double coverage is harmless.
// ---------------------------------------------------------------------------
__global__ void __launch_bounds__(256, 1)
triplet_main_kernel(const float* __restrict__ x) {
    extern __shared__ float smem[];
    float* As    = smem;                       // [128][130]
    float* Bs0   = smem + TILE_F;              // [128][130]
    float* Bs1   = smem + 2 * TILE_F;          // [128][130]
    float* sqis  = smem + 3 * TILE_F;          // [128]
    int*   labis = (int*)(sqis + BM);          // [128]
    float* sqjs  = (float*)(labis + BM);       // [2][128]
    int*   labjs = (int*)(sqjs + 2 * BN);      // [2][128]
    float* colAp = (float*)(labjs + 2 * BN);   // [8][128]
    float* colAn = colAp + 8 * BN;             // [8][128]

    const int tid = threadIdx.x;
    const int tx = tid & 15, ty = tid >> 4;

    const unsigned As_u   = smem_u32(As);
    const unsigned Bs0_u  = smem_u32(Bs0);
    const unsigned Bs1_u  = smem_u32(Bs1);
    const unsigned sqis_u = smem_u32(sqis);
    const unsigned labis_u = smem_u32(labis);
    const unsigned sqjs_u = smem_u32(sqjs);
    const unsigned labjs_u = smem_u32(labjs);

    // Static contiguous unit range for this CTA (row-major triangle order
    // keeps consecutive units on the same ti -> A tile reuse).
    int u0 = (int)((long long)blockIdx.x * NUNITS / gridDim.x);
    int u1 = (int)((long long)(blockIdx.x + 1) * NUNITS / gridDim.x);
    if (u0 >= u1) return;

    int ti = 0, rem = u0;
    while (rem >= NTILES - ti) { rem -= NTILES - ti; ti++; }
    int tj = ti + rem;

    // Prologue group: A tile + A meta + B(u0) tile + B meta
    load_tile_async(As_u, x, ti * BM, tid);
    load_tile_async(Bs0_u, x, tj * BN, tid);
    if (tid < BM) {
        cp4(sqis_u + tid * 4,  g_sq  + ti * BM + tid);
        cp4(labis_u + tid * 4, g_lab + ti * BM + tid);
        cp4(sqjs_u + tid * 4,  g_sq  + tj * BN + tid);
        cp4(labjs_u + tid * 4, g_lab + tj * BN + tid);
    }
    cp_commit();

    int curti = ti;

    for (int u = u0; u < u1; ++u) {
        const int buf = (u - u0) & 1;
        int nti = ti, ntj = tj + 1;
        if (ntj == NTILES) { nti = ti + 1; ntj = nti; }
        const bool has_next = (u + 1 < u1);

        // Prefetch next B tile (async; lands while we compute on current).
        if (has_next) {
            load_tile_async(buf ? Bs0_u : Bs1_u, x, ntj * BN, tid);
            if (tid < BN) {
                cp4(sqjs_u + ((buf ^ 1) * BN + tid) * 4,  g_sq  + ntj * BN + tid);
                cp4(labjs_u + ((buf ^ 1) * BN + tid) * 4, g_lab + ntj * BN + tid);
            }
            cp_commit();
            cp_wait1();   // current buffer's group has completed
        } else {
            cp_wait0();
        }
        __syncthreads();

        // ---- GEMM: acc[r][c] packed (even-k, odd-k) partial sums ----
        u64 acc[8][8];
#pragma unroll
        for (int r = 0; r < 8; r++)
#pragma unroll
            for (int c = 0; c < 8; c++) acc[r][c] = 0ull;

        const u64* A64 = reinterpret_cast<const u64*>(As) + ty * RSTRIDE64;
        const u64* B64 = reinterpret_cast<const u64*>(buf ? Bs1 : Bs0) + tx * RSTRIDE64;

#pragma unroll 2
        for (int k = 0; k < DIM / 2; ++k) {
            u64 a2[8], b2[8];
#pragma unroll
            for (int r = 0; r < 8; r++) a2[r] = A64[k + r * (16 * RSTRIDE64)];
#pragma unroll
            for (int c = 0; c < 8; c++) b2[c] = B64[k + c * (16 * RSTRIDE64)];
#pragma unroll
            for (int r = 0; r < 8; r++)
#pragma unroll
                for (int c = 0; c < 8; c++)
                    asm("fma.rn.f32x2 %0, %1, %2, %0;"
                        : "+l"(acc[r][c]) : "l"(a2[r]), "l"(b2[c]));
        }

        // ---- Epilogue: d^2 mining (row side + col side) ----
        float sjv[8]; int ljv[8];
#pragma unroll
        for (int c = 0; c < 8; c++) {
            sjv[c] = sqjs[buf * BN + tx + 16 * c];
            ljv[c] = labjs[buf * BN + tx + 16 * c];
        }
        float ap[8], an[8], apc[8], anc[8];
#pragma unroll
        for (int i = 0; i < 8; i++) {
            ap[i] = 0.0f;  an[i] = __int_as_float(0x7f800000);
            apc[i] = 0.0f; anc[i] = __int_as_float(0x7f800000);
        }
#pragma unroll
        for (int r = 0; r < 8; r++) {
            float si = sqis[ty + 16 * r];
            int   li = labis[ty + 16 * r];
#pragma unroll
            for (int c = 0; c < 8; c++) {
                float2 p = *reinterpret_cast<float2*>(&acc[r][c]);
                float d2 = fmaf(-2.0f, p.x + p.y, si + sjv[c]);
                d2 = fmaxf(d2, 1e-12f);
                if (li == ljv[c]) { ap[r] = fmaxf(ap[r], d2); apc[c] = fmaxf(apc[c], d2); }
                else              { an[r] = fminf(an[r], d2); anc[c] = fminf(anc[c], d2); }
            }
        }

        // Row side: reduce over the 16 tx-lanes (lanes 0-15 / 16-31 of a warp
        // hold the same rows), then atomics. Values > 0 => uint order == float order.
#pragma unroll
        for (int o = 8; o; o >>= 1)
#pragma unroll
            for (int r = 0; r < 8; r++) {
                ap[r] = fmaxf(ap[r], __shfl_xor_sync(0xffffffffu, ap[r], o));
                an[r] = fminf(an[r], __shfl_xor_sync(0xffffffffu, an[r], o));
            }
        if (tx == 0) {
#pragma unroll
            for (int r = 0; r < 8; r++) {
                int row = ti * BM + ty + 16 * r;
                atomicMax(&g_ap2[row], __float_as_uint(ap[r]));
                atomicMin(&g_an2[row], __float_as_uint(an[r]));
            }
        }

        // Col side: fold the ty-pair within each warp, stage per-warp partials
        // in smem, combine across 8 warps, atomics to g[tj..].
#pragma unroll
        for (int c = 0; c < 8; c++) {
            apc[c] = fmaxf(apc[c], __shfl_xor_sync(0xffffffffu, apc[c], 16));
            anc[c] = fminf(anc[c], __shfl_xor_sync(0xffffffffu, anc[c], 16));
        }
        if (((tid >> 4) & 1) == 0) {
            int w = tid >> 5;
#pragma unroll
            for (int c = 0; c < 8; c++) {
                colAp[w * BN + tx + 16 * c] = apc[c];
                colAn[w * BN + tx + 16 * c] = anc[c];
            }
        }
        __syncthreads();
        if (tid < BN) {
            float ca = colAp[tid], cn = colAn[tid];
#pragma unroll
            for (int w = 1; w < 8; w++) {
                ca = fmaxf(ca, colAp[w * BN + tid]);
                cn = fminf(cn, colAn[w * BN + tid]);
            }
            atomicMax(&g_ap2[tj * BN + tid], __float_as_uint(ca));
            atomicMin(&g_an2[tj * BN + tid], __float_as_uint(cn));
        }
        __syncthreads();   // colAp/colAn reusable; As safe to overwrite; Bs swap safe

        // A tile changes (rare): synchronous reload.
        if (has_next && nti != curti) {
            load_tile_plain(As, x, nti * BM, tid);
            if (tid < BM) {
                sqis[tid]  = g_sq[nti * BM + tid];
                labis[tid] = g_lab[nti * BM + tid];
            }
            curti = nti;
            __syncthreads();
        }
        ti = nti; tj = ntj;
    }
}

// ---------------------------------------------------------------------------
// Finalize: sqrt the mined d^2, margin ranking loss + precision means.
// ---------------------------------------------------------------------------
__global__ void finalize_kernel(float* __restrict__ out, int out_size) {
    __shared__ float sl[256], sp[256];
    float loss = 0.0f, prec = 0.0f;
    for (int i = threadIdx.x; i < NROWS; i += 256) {
        float dap = sqrtf(__uint_as_float(g_ap2[i]));
        float dan = sqrtf(__uint_as_float(g_an2[i]));
        loss += fmaxf(0.0f, MARGIN_F - (dan - dap));
        prec += (dan > dap) ? 1.0f : 0.0f;
    }
    sl[threadIdx.x] = loss;
    sp[threadIdx.x] = prec;
    __syncthreads();
#pragma unroll
    for (int s = 128; s > 0; s >>= 1) {
        if (threadIdx.x < s) {
            sl[threadIdx.x] += sl[threadIdx.x + s];
            sp[threadIdx.x] += sp[threadIdx.x + s];
        }
        __syncthreads();
    }
    if (threadIdx.x == 0) {
        out[0] = sl[0] / (float)NROWS;
        if (out_size > 1) out[1] = sp[0] / (float)NROWS;
    }
}

// ---------------------------------------------------------------------------
extern "C" void kernel_launch(void* const* d_in, const int* in_sizes, int n_in,
                              void* d_out, int out_size) {
    const float* x   = (const float*)d_in[0];
    const int*   t32 = (const int*)d_in[1];
    (void)in_sizes; (void)n_in;

    const int smem_bytes =
        (3 * TILE_F + BM /*sqis*/ + BM /*labis*/ + 2 * BN /*sqjs*/ +
         2 * BN /*labjs*/ + 8 * BN /*colAp*/ + 8 * BN /*colAn*/) * 4;
    cudaFuncSetAttribute(triplet_main_kernel,
                         cudaFuncAttributeMaxDynamicSharedMemorySize, smem_bytes);

    prep_labels_kernel<<<1, 256>>>(t32);
    sq_kernel<<<NROWS * 32 / 256, 256>>>(x);
    init_kernel<<<NROWS / 256, 256>>>();
    triplet_main_kernel<<<GRID_MAIN, 256, smem_bytes>>>(x);
    finalize_kernel<<<1, 256>>>((float*)d_out, out_size);
}

// round 7
// speedup vs baseline: 2.2088x; 1.0622x over previous
#include <cuda_runtime.h>
#include <cstdint>

#define NROWS 8192
#define DIM   128
#define BM    128
#define BN    128
#define NTILES (NROWS / BN)                  // 64
#define NUNITS (NTILES * (NTILES + 1) / 2)   // 2080 triangle tile-pairs
#define GRID_MAIN 148
#define RSTRIDE   132                        // floats/row: 132*4B=528B, /16=33 odd -> LDS.128 conflict-free
#define TILE_F (BM * RSTRIDE)                // 16896 floats per tile
#define MARGIN_F 0.3f

typedef unsigned long long u64;

// Scratch (device globals; no allocations allowed)
__device__ unsigned int g_ap2[NROWS];   // max same-label d^2 (float bits)
__device__ unsigned int g_an2[NROWS];   // min diff-label d^2 (float bits)
__device__ float        g_sq[NROWS];    // ||x_i||^2
__device__ int          g_lab[NROWS];   // normalized labels (int32)
__device__ unsigned int g_done;         // last-CTA election (reset each launch)

// ---------------------------------------------------------------------------
// Helpers
// ---------------------------------------------------------------------------
__device__ __forceinline__ unsigned smem_u32(const void* p) {
    unsigned r;
    asm("{ .reg .u64 t; cvta.to.shared.u64 t, %1; cvt.u32.u64 %0, t; }"
        : "=r"(r) : "l"(p));
    return r;
}
__device__ __forceinline__ void cp16(unsigned dst, const void* src) {
    asm volatile("cp.async.cg.shared.global [%0], [%1], 16;" :: "r"(dst), "l"(src));
}
__device__ __forceinline__ void cp4(unsigned dst, const void* src) {
    asm volatile("cp.async.ca.shared.global [%0], [%1], 4;" :: "r"(dst), "l"(src));
}
__device__ __forceinline__ void cp_commit() { asm volatile("cp.async.commit_group;"); }
__device__ __forceinline__ void cp_wait0()  { asm volatile("cp.async.wait_group 0;" ::: "memory"); }
__device__ __forceinline__ void cp_wait1()  { asm volatile("cp.async.wait_group 1;" ::: "memory"); }
__device__ __forceinline__ void cp_wait2()  { asm volatile("cp.async.wait_group 2;" ::: "memory"); }

// ---------------------------------------------------------------------------
// Fused prep: init mining buffers + row norms + label normalization.
// grid = 1024 x 256 (one warp per row for sq).
// ---------------------------------------------------------------------------
__global__ void prep_kernel(const float* __restrict__ x, const int* __restrict__ t32) {
    int gid = blockIdx.x * 256 + threadIdx.x;
    if (gid < NROWS) { g_ap2[gid] = 0u; g_an2[gid] = 0x7f800000u; }

    int gwarp = gid >> 5;          // exactly 8192 warps
    int lane  = gid & 31;
    float4 v = reinterpret_cast<const float4*>(x + (size_t)gwarp * DIM)[lane];
    float s = v.x * v.x + v.y * v.y + v.z * v.z + v.w * v.w;
#pragma unroll
    for (int o = 16; o; o >>= 1) s += __shfl_xor_sync(0xffffffffu, s, o);
    if (lane == 0) g_sq[gwarp] = s;

    if (blockIdx.x == 0) {
        // targets may be int64 (odd int32 words all zero) or int32
        __shared__ int s_all64;
        if (threadIdx.x == 0) s_all64 = 1;
        __syncthreads();
        int local = 1;
        for (int i = threadIdx.x; i < 4096; i += 256)
            if (t32[2 * i + 1] != 0) local = 0;
        if (!local) atomicAnd(&s_all64, 0);
        __syncthreads();
        const bool is64 = (s_all64 != 0);
        for (int i = threadIdx.x; i < NROWS; i += 256)
            g_lab[i] = is64 ? t32[2 * i] : t32[i];
    }
}

// ---------------------------------------------------------------------------
// Tile loader: global row-major [rows][128] -> smem rows of stride 132 floats.
// All offsets 16B-aligned (528 = 33*16).
// ---------------------------------------------------------------------------
__device__ __forceinline__ void load_tile_async(unsigned dst_u32,
                                                const float* __restrict__ x,
                                                int rowbase, int tid) {
#pragma unroll
    for (int i = 0; i < 16; i++) {
        int idx = tid + i * 256;      // 0..4095
        int row = idx >> 5;           // 0..127
        int q   = idx & 31;           // float4 chunk
        cp16(dst_u32 + (unsigned)(row * RSTRIDE + q * 4) * 4u,
             x + (size_t)(rowbase + row) * DIM + q * 4);
    }
}

// ---------------------------------------------------------------------------
// Main persistent kernel: triangle tile-pairs (ti <= tj), packed f32x2 FMA,
// LDS.128 fragments, async A refill at row crossings, inline finalize.
// ---------------------------------------------------------------------------
__global__ void __launch_bounds__(256, 1)
triplet_main_kernel(const float* __restrict__ x, float* __restrict__ out, int out_size) {
    extern __shared__ float smem[];
    float* As    = smem;                       // [128][132]
    float* Bs0   = smem + TILE_F;
    float* Bs1   = smem + 2 * TILE_F;
    float* sqis  = smem + 3 * TILE_F;          // [128]
    int*   labis = (int*)(sqis + BM);          // [128]
    float* sqjs  = (float*)(labis + BM);       // [2][128]
    int*   labjs = (int*)(sqjs + 2 * BN);      // [2][128]
    float* colAp = (float*)(labjs + 2 * BN);   // [8][128]
    float* colAn = colAp + 8 * BN;             // [8][128]

    const int tid = threadIdx.x;
    const int tx = tid & 15, ty = tid >> 4;

    const unsigned As_u    = smem_u32(As);
    const unsigned Bs0_u   = smem_u32(Bs0);
    const unsigned Bs1_u   = smem_u32(Bs1);
    const unsigned sqis_u  = smem_u32(sqis);
    const unsigned labis_u = smem_u32(labis);
    const unsigned sqjs_u  = smem_u32(sqjs);
    const unsigned labjs_u = smem_u32(labjs);

    // Static contiguous unit range (row-major triangle order -> A-tile reuse).
    int u0 = (int)((long long)blockIdx.x * NUNITS / gridDim.x);
    int u1 = (int)((long long)(blockIdx.x + 1) * NUNITS / gridDim.x);

    int ti = 0, rem = u0;
    while (rem >= NTILES - ti) { rem -= NTILES - ti; ti++; }
    int tj = ti + rem;

    // Prologue group: A tile + B(u0) tile + meta
    load_tile_async(As_u, x, ti * BM, tid);
    load_tile_async(Bs0_u, x, tj * BN, tid);
    if (tid < BM) {
        cp4(sqis_u + tid * 4,  g_sq  + ti * BM + tid);
        cp4(labis_u + tid * 4, g_lab + ti * BM + tid);
        cp4(sqjs_u + tid * 4,  g_sq  + tj * BN + tid);
        cp4(labjs_u + tid * 4, g_lab + tj * BN + tid);
    }
    cp_commit();

    bool alias = false;  // current unit reads A from its B buffer (fresh diagonal)

    for (int u = u0; u < u1; ++u) {
        const int buf = (u - u0) & 1;
        int nti = ti, ntj = tj + 1;
        if (ntj == NTILES) { nti = ti + 1; ntj = nti; }
        const bool has_next = (u + 1 < u1);

        int ncommit = 0;
        if (has_next) {
            load_tile_async(buf ? Bs0_u : Bs1_u, x, ntj * BN, tid);
            if (tid < BN) {
                cp4(sqjs_u + ((buf ^ 1) * BN + tid) * 4,  g_sq  + ntj * BN + tid);
                cp4(labjs_u + ((buf ^ 1) * BN + tid) * 4, g_lab + ntj * BN + tid);
            }
            cp_commit(); ncommit++;
        }
        // Aliased diagonal: As is idle this unit -> refill it (row ti's A) async,
        // but only if a same-row (non-diagonal) unit will actually use it.
        if (alias && has_next && nti == ti) {
            load_tile_async(As_u, x, ti * BM, tid);
            if (tid < BM) {
                cp4(sqis_u + tid * 4,  g_sq  + ti * BM + tid);
                cp4(labis_u + tid * 4, g_lab + ti * BM + tid);
            }
            cp_commit(); ncommit++;
        }
        // Everything committed before this iteration must be complete.
        if (ncommit == 0)      cp_wait0();
        else if (ncommit == 1) cp_wait1();
        else                   cp_wait2();
        __syncthreads();

        const float* bbuf  = buf ? Bs1 : Bs0;
        const float* abuf  = alias ? bbuf : As;
        const float* sqip  = alias ? (sqjs + buf * BN)  : sqis;
        const int*   labip = alias ? (labjs + buf * BN) : labis;

        // ---- GEMM: acc[r][c] holds packed (even-k, odd-k) partial sums ----
        u64 acc[8][8];
#pragma unroll
        for (int r = 0; r < 8; r++)
#pragma unroll
            for (int c = 0; c < 8; c++) acc[r][c] = 0ull;

        const char* aB = (const char*)abuf + ty * (RSTRIDE * 4);
        const char* bB = (const char*)bbuf + tx * (RSTRIDE * 4);

#pragma unroll 2
        for (int k4 = 0; k4 < DIM / 4; ++k4) {
            u64 a0[8], a1[8], b0[8], b1[8];
#pragma unroll
            for (int r = 0; r < 8; r++) {
                double2 v = *(const double2*)(aB + r * (16 * RSTRIDE * 4) + k4 * 16);
                a0[r] = __double_as_longlong(v.x);
                a1[r] = __double_as_longlong(v.y);
            }
#pragma unroll
            for (int c = 0; c < 8; c++) {
                double2 v = *(const double2*)(bB + c * (16 * RSTRIDE * 4) + k4 * 16);
                b0[c] = __double_as_longlong(v.x);
                b1[c] = __double_as_longlong(v.y);
            }
            // Two sweeps so the same acc register is never hit back-to-back.
#pragma unroll
            for (int r = 0; r < 8; r++)
#pragma unroll
                for (int c = 0; c < 8; c++)
                    asm("fma.rn.f32x2 %0, %1, %2, %0;"
                        : "+l"(acc[r][c]) : "l"(a0[r]), "l"(b0[c]));
#pragma unroll
            for (int r = 0; r < 8; r++)
#pragma unroll
                for (int c = 0; c < 8; c++)
                    asm("fma.rn.f32x2 %0, %1, %2, %0;"
                        : "+l"(acc[r][c]) : "l"(a1[r]), "l"(b1[c]));
        }

        // ---- Epilogue: d^2 mining, both row (i) and column (j) sides ----
        float sjv[8]; int ljv[8];
#pragma unroll
        for (int c = 0; c < 8; c++) {
            sjv[c] = sqjs[buf * BN + tx + 16 * c];
            ljv[c] = labjs[buf * BN + tx + 16 * c];
        }
        float ap[8], an[8], apc[8], anc[8];
#pragma unroll
        for (int i = 0; i < 8; i++) {
            ap[i] = 0.0f;  an[i] = __int_as_float(0x7f800000);
            apc[i] = 0.0f; anc[i] = __int_as_float(0x7f800000);
        }
#pragma unroll
        for (int r = 0; r < 8; r++) {
            float si = sqip[ty + 16 * r];
            int   li = labip[ty + 16 * r];
#pragma unroll
            for (int c = 0; c < 8; c++) {
                float2 p = *reinterpret_cast<float2*>(&acc[r][c]);
                float d2 = fmaf(-2.0f, p.x + p.y, si + sjv[c]);
                d2 = fmaxf(d2, 1e-12f);
                if (li == ljv[c]) { ap[r] = fmaxf(ap[r], d2); apc[c] = fmaxf(apc[c], d2); }
                else              { an[r] = fminf(an[r], d2); anc[c] = fminf(anc[c], d2); }
            }
        }

        // Row side: reduce over 16 tx-lanes, then atomics (d2 > 0 -> uint order ok)
#pragma unroll
        for (int o = 8; o; o >>= 1)
#pragma unroll
            for (int r = 0; r < 8; r++) {
                ap[r] = fmaxf(ap[r], __shfl_xor_sync(0xffffffffu, ap[r], o));
                an[r] = fminf(an[r], __shfl_xor_sync(0xffffffffu, an[r], o));
            }
        if (tx == 0) {
#pragma unroll
            for (int r = 0; r < 8; r++) {
                int row = ti * BM + ty + 16 * r;
                atomicMax(&g_ap2[row], __float_as_uint(ap[r]));
                atomicMin(&g_an2[row], __float_as_uint(an[r]));
            }
        }

        // Col side: fold ty-pair in each warp, stage per-warp, combine, atomics.
#pragma unroll
        for (int c = 0; c < 8; c++) {
            apc[c] = fmaxf(apc[c], __shfl_xor_sync(0xffffffffu, apc[c], 16));
            anc[c] = fminf(anc[c], __shfl_xor_sync(0xffffffffu, anc[c], 16));
        }
        if (((tid >> 4) & 1) == 0) {
            int w = tid >> 5;
#pragma unroll
            for (int c = 0; c < 8; c++) {
                colAp[w * BN + tx + 16 * c] = apc[c];
                colAn[w * BN + tx + 16 * c] = anc[c];
            }
        }
        __syncthreads();
        if (tid < BN) {
            float ca = colAp[tid], cn = colAn[tid];
#pragma unroll
            for (int w = 1; w < 8; w++) {
                ca = fmaxf(ca, colAp[w * BN + tid]);
                cn = fminf(cn, colAn[w * BN + tid]);
            }
            atomicMax(&g_ap2[tj * BN + tid], __float_as_uint(ca));
            atomicMin(&g_an2[tj * BN + tid], __float_as_uint(cn));
        }
        __syncthreads();

        alias = has_next && (nti != ti);  // next unit is a fresh diagonal
        ti = nti; tj = ntj;
    }

    // ---- Inline finalize: last CTA computes loss + precision ----
    __threadfence();
    __syncthreads();
    __shared__ unsigned s_rank;
    if (tid == 0) s_rank = atomicAdd(&g_done, 1u);
    __syncthreads();
    if (s_rank == (unsigned)(gridDim.x - 1)) {
        float loss = 0.0f, prec = 0.0f;
        for (int i = tid; i < NROWS; i += 256) {
            float dap = sqrtf(__uint_as_float(__ldcg(&g_ap2[i])));
            float dan = sqrtf(__uint_as_float(__ldcg(&g_an2[i])));
            loss += fmaxf(0.0f, MARGIN_F - (dan - dap));
            prec += (dan > dap) ? 1.0f : 0.0f;
        }
        colAp[tid] = loss;
        colAn[tid] = prec;
        __syncthreads();
#pragma unroll
        for (int s = 128; s > 0; s >>= 1) {
            if (tid < s) {
                colAp[tid] += colAp[tid + s];
                colAn[tid] += colAn[tid + s];
            }
            __syncthreads();
        }
        if (tid == 0) {
            out[0] = colAp[0] / (float)NROWS;
            if (out_size > 1) out[1] = colAn[0] / (float)NROWS;
            g_done = 0;  // reset for next graph replay
        }
    }
}

// ---------------------------------------------------------------------------
extern "C" void kernel_launch(void* const* d_in, const int* in_sizes, int n_in,
                              void* d_out, int out_size) {
    const float* x   = (const float*)d_in[0];
    const int*   t32 = (const int*)d_in[1];
    (void)in_sizes; (void)n_in;

    const int smem_bytes =
        (3 * TILE_F + BM + BM + 2 * BN + 2 * BN + 8 * BN + 8 * BN) * 4;
    cudaFuncSetAttribute(triplet_main_kernel,
                         cudaFuncAttributeMaxDynamicSharedMemorySize, smem_bytes);

    prep_kernel<<<NROWS * 32 / 256, 256>>>(x, t32);
    triplet_main_kernel<<<GRID_MAIN, 256, smem_bytes>>>(x, (float*)d_out, out_size);
}